// round 5
// baseline (speedup 1.0000x reference)
#include <cuda_runtime.h>
#include <math.h>

#define NN 50000
#define EE 800000
#define NF 128
#define NH 8
#define F1 256   // NH*NCH
#define NCLS 40

__device__ float g_h1[NN * F1];
__device__ float g_h2[NN * F1];
__device__ float g_h3[NN * NCLS];
__device__ float g_a1s[NN * NH];
__device__ float g_a1d[NN * NH];
__device__ float g_a2s[NN];
__device__ float g_a2d[NN];
__device__ float g_ea[(size_t)EE * NH];   // a1s gathered per edge (CSR order)
__device__ float g_ea2[EE];               // a2s gathered per edge
__device__ float g_Wa1T[16][NF];          // folded W1*att1 (transposed) [o][k]
__device__ float g_Wa2T[2][F1];           // folded W2*att2 (transposed)
__device__ int   g_deg[NN];
__device__ int   g_rowstart[NN + 1];
__device__ int   g_cursor[NN];
__device__ int   g_csr[EE];
__device__ int   g_is64;

__device__ __forceinline__ float lrelu(float x) { return x > 0.f ? x : 0.2f * x; }

// ---------------- fold attention vectors through the weight matrices ----------------
__global__ __launch_bounds__(256) void k_fold(const float* __restrict__ W1,
                                              const float* __restrict__ a1sw,
                                              const float* __restrict__ a1dw,
                                              const float* __restrict__ W2,
                                              const float* __restrict__ a2sw,
                                              const float* __restrict__ a2dw) {
    int tid = threadIdx.x;
    // Wa1T[o][k], o in [0,16): o<8 -> src head o ; o>=8 -> dst head o-8
    for (int idx = tid; idx < 16 * NF; idx += 256) {
        int o = idx / NF, k = idx % NF;
        int h = o & 7;
        const float* av = (o < 8) ? a1sw : a1dw;
        float s = 0.f;
        for (int c = 0; c < 32; c++)
            s = fmaf(W1[k * F1 + h * 32 + c], av[h * 32 + c], s);
        g_Wa1T[o][k] = s;
    }
    // Wa2T[o][k], o in {0,1}
    for (int idx = tid; idx < 2 * F1; idx += 256) {
        int o = idx / F1, k = idx % F1;
        const float* av = (o == 0) ? a2sw : a2dw;
        float s = 0.f;
        for (int c = 0; c < NCLS; c++)
            s = fmaf(W2[k * NCLS + c], av[c], s);
        g_Wa2T[o][k] = s;
    }
}

// ---------------- init: zero degree + detect edge_index dtype ----------------
__global__ void k_init(const void* ei) {
    int i = blockIdx.x * blockDim.x + threadIdx.x;
    if (i < NN) g_deg[i] = 0;
    if (i == 0) {
        const unsigned long long* p = (const unsigned long long*)ei;
        int ok = 1;
        for (int j = 0; j < 64; j++)
            if (p[j] >= (unsigned long long)NN) ok = 0;
        g_is64 = ok;
    }
}

__device__ __forceinline__ int edge_val(const void* ei, long long idx, int is64) {
    return is64 ? (int)((const long long*)ei)[idx] : ((const int*)ei)[idx];
}

__global__ void k_deg(const void* ei) {
    int e = blockIdx.x * blockDim.x + threadIdx.x;
    if (e >= EE) return;
    int d = edge_val(ei, (long long)EE + e, g_is64);
    atomicAdd(&g_deg[d], 1);
}

__global__ void k_scan() {   // single block, 1024 threads
    __shared__ int sh[1024];
    const int ITEMS = 49;
    int tid = threadIdx.x;
    int start = tid * ITEMS;
    int lsum = 0;
    for (int i = 0; i < ITEMS; i++) {
        int idx = start + i;
        if (idx < NN) lsum += g_deg[idx];
    }
    sh[tid] = lsum;
    __syncthreads();
    for (int off = 1; off < 1024; off <<= 1) {
        int t = (tid >= off) ? sh[tid - off] : 0;
        __syncthreads();
        sh[tid] += t;
        __syncthreads();
    }
    int run = sh[tid] - lsum;
    for (int i = 0; i < ITEMS; i++) {
        int idx = start + i;
        if (idx < NN) {
            g_rowstart[idx] = run;
            g_cursor[idx]   = run;
            run += g_deg[idx];
        }
    }
    if (tid == 1023) g_rowstart[NN] = sh[1023];
}

// scatter: build csr AND pre-gather the 8 per-head src logits per edge
__global__ void k_scatter(const void* ei) {
    int e = blockIdx.x * blockDim.x + threadIdx.x;
    if (e >= EE) return;
    int is64 = g_is64;
    int s = edge_val(ei, e, is64);
    int d = edge_val(ei, (long long)EE + e, is64);
    int pos = atomicAdd(&g_cursor[d], 1);
    g_csr[pos] = s;
    const float4* ps = (const float4*)(g_a1s + s * NH);
    float4 v0 = ps[0], v1 = ps[1];
    float4* pe = (float4*)(g_ea + (size_t)pos * NH);
    pe[0] = v0; pe[1] = v1;
}

// ---------------- a1s/a1d = x @ Wa1T (warp per node) ----------------
__global__ __launch_bounds__(256) void k_att1lin(const float* __restrict__ x) {
    __shared__ float wa[16][NF];
    int tid = threadIdx.x;
    for (int idx = tid; idx < 16 * NF; idx += 256)
        ((float*)wa)[idx] = ((const float*)g_Wa1T)[idx];
    __syncthreads();
    int n = blockIdx.x * 8 + (tid >> 5);
    if (n >= NN) return;
    int lane = tid & 31;
    float4 v = ((const float4*)(x + (size_t)n * NF))[lane];
    float r[16];
#pragma unroll
    for (int o = 0; o < 16; o++) {
        float4 w = ((const float4*)&wa[o][0])[lane];
        r[o] = v.x * w.x + v.y * w.y + v.z * w.z + v.w * w.w;
    }
#pragma unroll
    for (int off = 16; off; off >>= 1)
#pragma unroll
        for (int o = 0; o < 16; o++)
            r[o] += __shfl_xor_sync(0xffffffffu, r[o], off);
    if (lane == 0) {
#pragma unroll
        for (int o = 0; o < 8; o++) {
            g_a1s[n * NH + o] = r[o];
            g_a1d[n * NH + o] = r[8 + o];
        }
    }
}

// ---------------- GEMM1: h1 = x @ W1 (pure) ----------------
__global__ __launch_bounds__(256) void k_gemm1(const float* __restrict__ x,
                                               const float* __restrict__ W) {
    __shared__ float xs[32][65];
    __shared__ float ws[32][256];
    int tid = threadIdx.x;
    int tx = tid & 31, ty = tid >> 5;
    int m0 = blockIdx.x * 64;
    float acc[8][8];
#pragma unroll
    for (int i = 0; i < 8; i++)
#pragma unroll
        for (int j = 0; j < 8; j++) acc[i][j] = 0.f;

    for (int ks = 0; ks < NF; ks += 32) {
        {
            int r  = tid >> 2;
            int c4 = (tid & 3) << 3;
            int gm = m0 + r;
            float4 v0, v1;
            if (gm < NN) {
                const float4* px = (const float4*)(x + (long long)gm * NF + ks + c4);
                v0 = px[0]; v1 = px[1];
            } else {
                v0 = make_float4(0, 0, 0, 0); v1 = v0;
            }
            xs[c4 + 0][r] = v0.x; xs[c4 + 1][r] = v0.y;
            xs[c4 + 2][r] = v0.z; xs[c4 + 3][r] = v0.w;
            xs[c4 + 4][r] = v1.x; xs[c4 + 5][r] = v1.y;
            xs[c4 + 6][r] = v1.z; xs[c4 + 7][r] = v1.w;
        }
#pragma unroll
        for (int it = 0; it < 8; it++) {
            int f4 = it * 256 + tid;
            int k = f4 >> 6, c4 = f4 & 63;
            float4 wv = ((const float4*)(W + (long long)(ks + k) * F1))[c4];
            *((float4*)&ws[k][c4 << 2]) = wv;
        }
        __syncthreads();
#pragma unroll
        for (int k = 0; k < 32; k++) {
            float a[8], b[8];
#pragma unroll
            for (int i = 0; i < 8; i++) a[i] = xs[k][ty + 8 * i];
#pragma unroll
            for (int j = 0; j < 8; j++) b[j] = ws[k][tx + 32 * j];
#pragma unroll
            for (int i = 0; i < 8; i++)
#pragma unroll
                for (int j = 0; j < 8; j++) acc[i][j] = fmaf(a[i], b[j], acc[i][j]);
        }
        __syncthreads();
    }
#pragma unroll
    for (int i = 0; i < 8; i++) {
        int gm = m0 + ty + 8 * i;
        if (gm < NN) {
#pragma unroll
            for (int j = 0; j < 8; j++)
                g_h1[gm * F1 + tx + 32 * j] = acc[i][j];
        }
    }
}

// ---------------- layer-1: fused softmax + aggregation + bias + ELU ----------------
// block = node; warp = head; 32-edge cooperative chunks:
// all lanes prefetch csr+ea (coalesced), exp locally; then groups of 8 lanes
// consume 4 edges at a time via shfl broadcast + one LDG.128 per lane.
__global__ __launch_bounds__(256) void k_gather1(const float* __restrict__ b1) {
    int n = blockIdx.x;
    int tid = threadIdx.x;
    int h = tid >> 5;
    int lane = tid & 31;
    int g = lane >> 3, l = lane & 7;
    int off = h * 32 + l * 4;
    float ad = g_a1d[n * NH + h];
    float4 acc = make_float4(0.f, 0.f, 0.f, 0.f);
    float S = 0.f;
    if (g == 0) {   // self-loop handled by group 0
        float aself = __expf(lrelu(g_a1s[n * NH + h] + ad));
        float4 v = *(const float4*)(g_h1 + n * F1 + off);
        acc.x = aself * v.x; acc.y = aself * v.y;
        acc.z = aself * v.z; acc.w = aself * v.w;
        S = aself;
    }
    int rs = g_rowstart[n], re = g_rowstart[n + 1];
    for (int base = rs; base < re; base += 32) {
        int idx = base + lane;
        int sv = 0; float av = 0.f;
        if (idx < re) {
            sv = g_csr[idx];
            av = __expf(lrelu(g_ea[(size_t)idx * NH + h] + ad));
        }
        int cnt = min(32, re - base);
        for (int t0 = 0; t0 < cnt; t0 += 4) {
            int t = t0 + g;
            bool act = t < cnt;
            int sj   = __shfl_sync(0xffffffffu, sv, t & 31);
            float aj = __shfl_sync(0xffffffffu, av, t & 31);
            if (act) {
                float4 v = *(const float4*)(g_h1 + (size_t)sj * F1 + off);
                acc.x = fmaf(aj, v.x, acc.x);
                acc.y = fmaf(aj, v.y, acc.y);
                acc.z = fmaf(aj, v.z, acc.z);
                acc.w = fmaf(aj, v.w, acc.w);
                S += aj;
            }
        }
    }
#pragma unroll
    for (int o = 8; o <= 16; o <<= 1) {
        acc.x += __shfl_xor_sync(0xffffffffu, acc.x, o);
        acc.y += __shfl_xor_sync(0xffffffffu, acc.y, o);
        acc.z += __shfl_xor_sync(0xffffffffu, acc.z, o);
        acc.w += __shfl_xor_sync(0xffffffffu, acc.w, o);
        S     += __shfl_xor_sync(0xffffffffu, S, o);
    }
    if (g == 0) {
        float sinv = 1.f / (S + 1e-16f);
        float4 bb = *(const float4*)(b1 + off);
        float4 r;
        r.x = acc.x * sinv + bb.x;
        r.y = acc.y * sinv + bb.y;
        r.z = acc.z * sinv + bb.z;
        r.w = acc.w * sinv + bb.w;
        r.x = (r.x > 0.f) ? r.x : expm1f(r.x);
        r.y = (r.y > 0.f) ? r.y : expm1f(r.y);
        r.z = (r.z > 0.f) ? r.z : expm1f(r.z);
        r.w = (r.w > 0.f) ? r.w : expm1f(r.w);
        *(float4*)(g_h2 + n * F1 + off) = r;
    }
}

// ---------------- a2s/a2d = h2 @ Wa2T (warp per node) ----------------
__global__ __launch_bounds__(256) void k_att2lin() {
    __shared__ float wa[2][F1];
    int tid = threadIdx.x;
    for (int idx = tid; idx < 2 * F1; idx += 256)
        ((float*)wa)[idx] = ((const float*)g_Wa2T)[idx];
    __syncthreads();
    int n = blockIdx.x * 8 + (tid >> 5);
    if (n >= NN) return;
    int lane = tid & 31;
    const float4* ph = (const float4*)(g_h2 + (size_t)n * F1);
    float4 v0 = ph[lane], v1 = ph[lane + 32];
    float r[2];
#pragma unroll
    for (int o = 0; o < 2; o++) {
        float4 w0 = ((const float4*)&wa[o][0])[lane];
        float4 w1 = ((const float4*)&wa[o][0])[lane + 32];
        r[o] = v0.x * w0.x + v0.y * w0.y + v0.z * w0.z + v0.w * w0.w
             + v1.x * w1.x + v1.y * w1.y + v1.z * w1.z + v1.w * w1.w;
    }
#pragma unroll
    for (int off = 16; off; off >>= 1) {
        r[0] += __shfl_xor_sync(0xffffffffu, r[0], off);
        r[1] += __shfl_xor_sync(0xffffffffu, r[1], off);
    }
    if (lane == 0) {
        g_a2s[n] = r[0];
        g_a2d[n] = r[1];
    }
}

// ---------------- pre-gather a2s per edge ----------------
__global__ void k_ea2() {
    int e = blockIdx.x * blockDim.x + threadIdx.x;
    if (e >= EE) return;
    g_ea2[e] = g_a2s[g_csr[e]];
}

// ---------------- GEMM2: h3 = h2 @ W2 (pure) ----------------
__global__ __launch_bounds__(256) void k_gemm2(const float* __restrict__ W2) {
    __shared__ float hs[32][129];
    __shared__ float ws2[32][40];
    int tid = threadIdx.x;
    int tx = tid & 7, ty = tid >> 3;
    int m0 = blockIdx.x * 128;
    float acc[4][5];
#pragma unroll
    for (int i = 0; i < 4; i++)
#pragma unroll
        for (int j = 0; j < 5; j++) acc[i][j] = 0.f;

    for (int ks = 0; ks < F1; ks += 32) {
#pragma unroll
        for (int it = 0; it < 4; it++) {
            int f4 = it * 256 + tid;
            int r = f4 >> 3, c4 = f4 & 7;
            int gm = m0 + r;
            float4 v = make_float4(0, 0, 0, 0);
            if (gm < NN) v = *((const float4*)(g_h2 + gm * F1 + ks + (c4 << 2)));
            hs[(c4 << 2) + 0][r] = v.x; hs[(c4 << 2) + 1][r] = v.y;
            hs[(c4 << 2) + 2][r] = v.z; hs[(c4 << 2) + 3][r] = v.w;
        }
#pragma unroll
        for (int it = 0; it < 5; it++) {
            int idx = it * 256 + tid;
            int k = idx / 40, c = idx % 40;
            ws2[k][c] = W2[(ks + k) * NCLS + c];
        }
        __syncthreads();
#pragma unroll
        for (int k = 0; k < 32; k++) {
            float a[4], b[5];
#pragma unroll
            for (int i = 0; i < 4; i++) a[i] = hs[k][ty + 32 * i];
#pragma unroll
            for (int j = 0; j < 5; j++) b[j] = ws2[k][tx + 8 * j];
#pragma unroll
            for (int i = 0; i < 4; i++)
#pragma unroll
                for (int j = 0; j < 5; j++) acc[i][j] = fmaf(a[i], b[j], acc[i][j]);
        }
        __syncthreads();
    }
#pragma unroll
    for (int i = 0; i < 4; i++) {
        int gm = m0 + ty + 32 * i;
        if (gm >= NN) continue;
#pragma unroll
        for (int j = 0; j < 5; j++)
            g_h3[gm * NCLS + tx + 8 * j] = acc[i][j];
    }
}

// ---------------- layer-2: fused softmax + gather + bias + log_softmax ----------------
// one warp per node; 32-edge cooperative chunks like gather1.
__global__ __launch_bounds__(128) void k_gather2(const float* __restrict__ b2,
                                                 float* __restrict__ out) {
    int n = blockIdx.x * 4 + (threadIdx.x >> 5);
    if (n >= NN) return;
    int lane = threadIdx.x & 31;
    bool actc = lane < 20;
    float adn = g_a2d[n];
    float aself = __expf(lrelu(g_a2s[n] + adn));
    float S = aself;
    float2 acc = make_float2(0.f, 0.f);
    if (actc) {
        float2 v = *(const float2*)(g_h3 + n * NCLS + lane * 2);
        acc.x = aself * v.x; acc.y = aself * v.y;
    }
    int rs = g_rowstart[n], re = g_rowstart[n + 1];
    for (int base = rs; base < re; base += 32) {
        int idx = base + lane;
        int sv = 0; float av = 0.f;
        if (idx < re) {
            sv = g_csr[idx];
            av = __expf(lrelu(g_ea2[idx] + adn));
        }
        int cnt = min(32, re - base);
        for (int t = 0; t < cnt; t++) {
            int sj   = __shfl_sync(0xffffffffu, sv, t);
            float aj = __shfl_sync(0xffffffffu, av, t);
            S += aj;
            if (actc) {
                float2 v = *(const float2*)(g_h3 + (size_t)sj * NCLS + lane * 2);
                acc.x = fmaf(aj, v.x, acc.x);
                acc.y = fmaf(aj, v.y, acc.y);
            }
        }
    }
    float sinv = 1.f / (S + 1e-16f);
    float vx = -1e30f, vy = -1e30f;
    if (actc) {
        float2 bb = *(const float2*)(b2 + lane * 2);
        vx = acc.x * sinv + bb.x;
        vy = acc.y * sinv + bb.y;
    }
    float mx = fmaxf(vx, vy);
#pragma unroll
    for (int o = 16; o; o >>= 1) mx = fmaxf(mx, __shfl_xor_sync(0xffffffffu, mx, o));
    float s2 = actc ? (__expf(vx - mx) + __expf(vy - mx)) : 0.f;
#pragma unroll
    for (int o = 16; o; o >>= 1) s2 += __shfl_xor_sync(0xffffffffu, s2, o);
    float lg = logf(s2);
    if (actc) {
        float2 r; r.x = vx - mx - lg; r.y = vy - mx - lg;
        *(float2*)(out + n * NCLS + lane * 2) = r;
    }
}

// ---------------- launcher ----------------
extern "C" void kernel_launch(void* const* d_in, const int* in_sizes, int n_in,
                              void* d_out, int out_size) {
    const float* x    = (const float*)d_in[0];
    const void*  ei   = d_in[1];
    const float* W1   = (const float*)d_in[2];
    const float* a1sw = (const float*)d_in[3];
    const float* a1dw = (const float*)d_in[4];
    const float* b1   = (const float*)d_in[5];
    const float* W2   = (const float*)d_in[6];
    const float* a2sw = (const float*)d_in[7];
    const float* a2dw = (const float*)d_in[8];
    const float* b2   = (const float*)d_in[9];
    float* out = (float*)d_out;

    k_fold<<<1, 256>>>(W1, a1sw, a1dw, W2, a2sw, a2dw);         // 1
    k_init<<<(NN + 255) / 256, 256>>>(ei);                       // 2
    k_deg<<<(EE + 255) / 256, 256>>>(ei);                        // 3
    k_gemm1<<<(NN + 63) / 64, 256>>>(x, W1);                     // 4 (profiled slot)
    k_scan<<<1, 1024>>>();                                       // 5
    k_att1lin<<<(NN + 7) / 8, 256>>>(x);                         // 6
    k_scatter<<<(EE + 255) / 256, 256>>>(ei);                    // 7
    k_gather1<<<NN, 256>>>(b1);                                  // 8
    k_att2lin<<<(NN + 7) / 8, 256>>>();                          // 9
    k_ea2<<<(EE + 255) / 256, 256>>>();                          // 10
    k_gemm2<<<(NN + 127) / 128, 256>>>(W2);                      // 11
    k_gather2<<<(NN + 3) / 4, 128>>>(b2, out);                   // 12
}

// round 6
// speedup vs baseline: 1.2048x; 1.2048x over previous
#include <cuda_runtime.h>
#include <math.h>

#define NN 50000
#define EE 800000
#define NF 128
#define NH 8
#define F1 256   // NH*NCH
#define NCLS 40

__device__ float g_h1[NN * F1];
__device__ float g_h2[NN * F1];
__device__ float g_h3[NN * NCLS];
__device__ float g_a1s[NN * NH];
__device__ float g_a1d[NN * NH];
__device__ float g_a2s[NN];
__device__ float g_a2d[NN];
__device__ int   g_deg[NN];
__device__ int   g_rowstart[NN + 1];
__device__ int   g_cursor[NN];
__device__ int   g_csr[EE];
__device__ int   g_is64;

__device__ __forceinline__ float lrelu(float x) { return x > 0.f ? x : 0.2f * x; }

// ---------------- init: zero degree + detect edge_index dtype ----------------
__global__ void k_init(const void* ei) {
    int i = blockIdx.x * blockDim.x + threadIdx.x;
    if (i < NN) g_deg[i] = 0;
    if (i == 0) {
        const unsigned long long* p = (const unsigned long long*)ei;
        int ok = 1;
        for (int j = 0; j < 64; j++)
            if (p[j] >= (unsigned long long)NN) ok = 0;
        g_is64 = ok;
    }
}

__device__ __forceinline__ int edge_val(const void* ei, long long idx, int is64) {
    return is64 ? (int)((const long long*)ei)[idx] : ((const int*)ei)[idx];
}

// ---------------- CSR build ----------------
__global__ void k_deg(const void* ei) {
    int e = blockIdx.x * blockDim.x + threadIdx.x;
    if (e >= EE) return;
    int d = edge_val(ei, (long long)EE + e, g_is64);
    atomicAdd(&g_deg[d], 1);
}

__global__ void k_scan() {   // single block, 1024 threads
    __shared__ int sh[1024];
    const int ITEMS = 49;
    int tid = threadIdx.x;
    int start = tid * ITEMS;
    int lsum = 0;
    for (int i = 0; i < ITEMS; i++) {
        int idx = start + i;
        if (idx < NN) lsum += g_deg[idx];
    }
    sh[tid] = lsum;
    __syncthreads();
    for (int off = 1; off < 1024; off <<= 1) {
        int t = (tid >= off) ? sh[tid - off] : 0;
        __syncthreads();
        sh[tid] += t;
        __syncthreads();
    }
    int run = sh[tid] - lsum;
    for (int i = 0; i < ITEMS; i++) {
        int idx = start + i;
        if (idx < NN) {
            g_rowstart[idx] = run;
            g_cursor[idx]   = run;
            run += g_deg[idx];
        }
    }
    if (tid == 1023) g_rowstart[NN] = sh[1023];
}

__global__ void k_scatter(const void* ei) {
    int e = blockIdx.x * blockDim.x + threadIdx.x;
    if (e >= EE) return;
    int is64 = g_is64;
    int s = edge_val(ei, e, is64);
    int d = edge_val(ei, (long long)EE + e, is64);
    int pos = atomicAdd(&g_cursor[d], 1);
    g_csr[pos] = s;
}

// ---------------- GEMM1: h1 = x @ W1 + fused attention logits ----------------
// 64x256 block tile, 256 threads; thread tile: rows {ty*4+i, 32+ty*4+i},
// cols {tx*4+j, 128+tx*4+j}. Inner loop: 4 LDS.128 + 64 FFMA per k.
__global__ __launch_bounds__(256) void k_gemm1(const float* __restrict__ x,
                                               const float* __restrict__ W,
                                               const float* __restrict__ asw,
                                               const float* __restrict__ adw) {
    __shared__ float xs[32][68];    // [k][row], pad to 68 for 16B-aligned rows
    __shared__ float ws[32][256];   // [k][col]
    int tid = threadIdx.x;
    int tx = tid & 31, ty = tid >> 5;
    int m0 = blockIdx.x * 64;
    float acc[8][8];
#pragma unroll
    for (int i = 0; i < 8; i++)
#pragma unroll
        for (int j = 0; j < 8; j++) acc[i][j] = 0.f;

    for (int ks = 0; ks < NF; ks += 32) {
        {
            int r  = tid >> 2;
            int c4 = (tid & 3) << 3;
            int gm = m0 + r;
            float4 v0, v1;
            if (gm < NN) {
                const float4* px = (const float4*)(x + (long long)gm * NF + ks + c4);
                v0 = px[0]; v1 = px[1];
            } else {
                v0 = make_float4(0, 0, 0, 0); v1 = v0;
            }
            xs[c4 + 0][r] = v0.x; xs[c4 + 1][r] = v0.y;
            xs[c4 + 2][r] = v0.z; xs[c4 + 3][r] = v0.w;
            xs[c4 + 4][r] = v1.x; xs[c4 + 5][r] = v1.y;
            xs[c4 + 6][r] = v1.z; xs[c4 + 7][r] = v1.w;
        }
#pragma unroll
        for (int it = 0; it < 8; it++) {
            int f4 = it * 256 + tid;
            int k = f4 >> 6, c4 = f4 & 63;
            float4 wv = ((const float4*)(W + (long long)(ks + k) * F1))[c4];
            *((float4*)&ws[k][c4 << 2]) = wv;
        }
        __syncthreads();
#pragma unroll
        for (int k = 0; k < 32; k++) {
            const float4* xk = (const float4*)&xs[k][0];
            const float4* wk = (const float4*)&ws[k][0];
            float4 a0 = xk[ty];          // rows ty*4..+3 (warp-uniform: broadcast)
            float4 a1 = xk[8 + ty];      // rows 32+ty*4..+3
            float4 b0 = wk[tx];          // cols tx*4..+3
            float4 b1 = wk[32 + tx];     // cols 128+tx*4..+3
            float av[8] = {a0.x, a0.y, a0.z, a0.w, a1.x, a1.y, a1.z, a1.w};
            float bv[8] = {b0.x, b0.y, b0.z, b0.w, b1.x, b1.y, b1.z, b1.w};
#pragma unroll
            for (int i = 0; i < 8; i++)
#pragma unroll
                for (int j = 0; j < 8; j++)
                    acc[i][j] = fmaf(av[i], bv[j], acc[i][j]);
        }
        __syncthreads();
    }

    // attention weights for this thread's 8 columns
    int c_lo = tx * 4, c_hi = 128 + tx * 4;
    float was[8], wad[8];
#pragma unroll
    for (int j = 0; j < 4; j++) {
        was[j]     = asw[c_lo + j];
        was[4 + j] = asw[c_hi + j];
        wad[j]     = adw[c_lo + j];
        wad[4 + j] = adw[c_hi + j];
    }
    int hd = tx >> 3;   // head of c_lo block (uniform per 8-lane group); c_hi head = 4+hd

#pragma unroll
    for (int i = 0; i < 8; i++) {
        int gm = m0 + ((i < 4) ? (ty * 4 + i) : (32 + ty * 4 + (i - 4)));
        bool ok = gm < NN;
        if (ok) {
            float4 r0 = make_float4(acc[i][0], acc[i][1], acc[i][2], acc[i][3]);
            float4 r1 = make_float4(acc[i][4], acc[i][5], acc[i][6], acc[i][7]);
            *(float4*)(g_h1 + (size_t)gm * F1 + c_lo) = r0;
            *(float4*)(g_h1 + (size_t)gm * F1 + c_hi) = r1;
        }
        // per-head logits: reduce over the 8 lanes sharing a head (width-8 xor)
        float vs0 = 0.f, vd0 = 0.f, vs1 = 0.f, vd1 = 0.f;
#pragma unroll
        for (int j = 0; j < 4; j++) {
            vs0 = fmaf(acc[i][j], was[j], vs0);
            vd0 = fmaf(acc[i][j], wad[j], vd0);
            vs1 = fmaf(acc[i][4 + j], was[4 + j], vs1);
            vd1 = fmaf(acc[i][4 + j], wad[4 + j], vd1);
        }
#pragma unroll
        for (int o = 4; o; o >>= 1) {
            vs0 += __shfl_xor_sync(0xffffffffu, vs0, o);
            vd0 += __shfl_xor_sync(0xffffffffu, vd0, o);
            vs1 += __shfl_xor_sync(0xffffffffu, vs1, o);
            vd1 += __shfl_xor_sync(0xffffffffu, vd1, o);
        }
        if ((tx & 7) == 0 && ok) {
            g_a1s[gm * NH + hd]     = vs0;
            g_a1d[gm * NH + hd]     = vd0;
            g_a1s[gm * NH + 4 + hd] = vs1;
            g_a1d[gm * NH + 4 + hd] = vd1;
        }
    }
}

// ---------------- layer-1: fused softmax + aggregation + bias + ELU ----------------
// block = node (8 warps); warp = head; lanes in 4 groups of 8; group g -> edge e+g;
// each lane holds a float4 of channels -> one LDG.128 covers 4 edges x 128B.
__global__ __launch_bounds__(256) void k_gather1(const float* __restrict__ b1) {
    int n = blockIdx.x;
    int tid = threadIdx.x;
    int h = tid >> 5;
    int lane = tid & 31;
    int g = lane >> 3, l = lane & 7;
    int gbase = g << 3;
    int off = h * 32 + l * 4;
    float ad = g_a1d[n * NH + h];
    float4 acc = make_float4(0.f, 0.f, 0.f, 0.f);
    float S = 0.f;
    if (g == 0) {   // self-loop handled by group 0
        float aself = __expf(lrelu(g_a1s[n * NH + h] + ad));
        float4 v = *(const float4*)(g_h1 + n * F1 + off);
        acc.x = aself * v.x; acc.y = aself * v.y;
        acc.z = aself * v.z; acc.w = aself * v.w;
        S = aself;
    }
    int rs = g_rowstart[n], re = g_rowstart[n + 1];
    for (int e = rs; e < re; e += 4) {
        bool act = (e + g) < re;
        int s = 0; float a = 0.f;
        if (l == 0 && act) {
            s = g_csr[e + g];
            a = __expf(lrelu(g_a1s[s * NH + h] + ad));
        }
        s = __shfl_sync(0xffffffffu, s, gbase);
        a = __shfl_sync(0xffffffffu, a, gbase);
        if (act) {
            float4 v = *(const float4*)(g_h1 + (size_t)s * F1 + off);
            acc.x = fmaf(a, v.x, acc.x);
            acc.y = fmaf(a, v.y, acc.y);
            acc.z = fmaf(a, v.z, acc.z);
            acc.w = fmaf(a, v.w, acc.w);
            S += a;
        }
    }
#pragma unroll
    for (int o = 8; o <= 16; o <<= 1) {
        acc.x += __shfl_xor_sync(0xffffffffu, acc.x, o);
        acc.y += __shfl_xor_sync(0xffffffffu, acc.y, o);
        acc.z += __shfl_xor_sync(0xffffffffu, acc.z, o);
        acc.w += __shfl_xor_sync(0xffffffffu, acc.w, o);
        S     += __shfl_xor_sync(0xffffffffu, S, o);
    }
    if (g == 0) {
        float sinv = 1.f / (S + 1e-16f);
        float4 bb = *(const float4*)(b1 + off);
        float4 r;
        r.x = acc.x * sinv + bb.x;
        r.y = acc.y * sinv + bb.y;
        r.z = acc.z * sinv + bb.z;
        r.w = acc.w * sinv + bb.w;
        r.x = (r.x > 0.f) ? r.x : expm1f(r.x);
        r.y = (r.y > 0.f) ? r.y : expm1f(r.y);
        r.z = (r.z > 0.f) ? r.z : expm1f(r.z);
        r.w = (r.w > 0.f) ? r.w : expm1f(r.w);
        *(float4*)(g_h2 + n * F1 + off) = r;
    }
}

// ---------------- GEMM2: h3 = h2 @ W2 + a2 logits ----------------
// 128x40 tile, 256 threads; tx=tid&7 (5 cols), ty=tid>>3 (rows ty*4+i).
__global__ __launch_bounds__(256) void k_gemm2(const float* __restrict__ W2,
                                               const float* __restrict__ a2sw,
                                               const float* __restrict__ a2dw) {
    __shared__ float hs[32][132];   // [k][row], pad 132 for 16B alignment
    __shared__ float ws2[32][40];
    int tid = threadIdx.x;
    int tx = tid & 7, ty = tid >> 3;
    int m0 = blockIdx.x * 128;
    float acc[4][5];
#pragma unroll
    for (int i = 0; i < 4; i++)
#pragma unroll
        for (int j = 0; j < 5; j++) acc[i][j] = 0.f;

    for (int ks = 0; ks < F1; ks += 32) {
#pragma unroll
        for (int it = 0; it < 4; it++) {
            int f4 = it * 256 + tid;
            int r = f4 >> 3, c4 = f4 & 7;
            int gm = m0 + r;
            float4 v = make_float4(0, 0, 0, 0);
            if (gm < NN) v = *((const float4*)(g_h2 + (size_t)gm * F1 + ks + (c4 << 2)));
            hs[(c4 << 2) + 0][r] = v.x; hs[(c4 << 2) + 1][r] = v.y;
            hs[(c4 << 2) + 2][r] = v.z; hs[(c4 << 2) + 3][r] = v.w;
        }
#pragma unroll
        for (int it = 0; it < 5; it++) {
            int idx = it * 256 + tid;
            int k = idx / 40, c = idx % 40;
            ws2[k][c] = W2[(ks + k) * NCLS + c];
        }
        __syncthreads();
#pragma unroll
        for (int k = 0; k < 32; k++) {
            float4 a4 = ((const float4*)&hs[k][0])[ty];   // rows ty*4..+3
            float av[4] = {a4.x, a4.y, a4.z, a4.w};
            float b[5];
#pragma unroll
            for (int j = 0; j < 5; j++) b[j] = ws2[k][tx + 8 * j];
#pragma unroll
            for (int i = 0; i < 4; i++)
#pragma unroll
                for (int j = 0; j < 5; j++) acc[i][j] = fmaf(av[i], b[j], acc[i][j]);
        }
        __syncthreads();
    }
#pragma unroll
    for (int i = 0; i < 4; i++) {
        int gm = m0 + ty * 4 + i;
        if (gm >= NN) continue;
        float pa = 0.f, pd = 0.f;
#pragma unroll
        for (int j = 0; j < 5; j++) {
            int c = tx + 8 * j;
            g_h3[(size_t)gm * NCLS + c] = acc[i][j];
            pa = fmaf(acc[i][j], a2sw[c], pa);
            pd = fmaf(acc[i][j], a2dw[c], pd);
        }
#pragma unroll
        for (int o = 4; o; o >>= 1) {
            pa += __shfl_xor_sync(0xffffffffu, pa, o, 8);
            pd += __shfl_xor_sync(0xffffffffu, pd, o, 8);
        }
        if (tx == 0) {
            g_a2s[gm] = pa;
            g_a2d[gm] = pd;
        }
    }
}

// ---------------- layer-2: fused softmax + gather + bias + log_softmax ----------------
// one warp per node; lanes 0..19 hold 40 channels as float2; csr/a2s batched 4-wide.
__global__ __launch_bounds__(128) void k_gather2(const float* __restrict__ b2,
                                                 float* __restrict__ out) {
    int n = blockIdx.x * 4 + (threadIdx.x >> 5);
    if (n >= NN) return;
    int lane = threadIdx.x & 31;
    bool actc = lane < 20;
    float adn = g_a2d[n];
    float aself = __expf(lrelu(g_a2s[n] + adn));
    float S = aself;
    float2 acc = make_float2(0.f, 0.f);
    if (actc) {
        float2 v = *(const float2*)(g_h3 + n * NCLS + lane * 2);
        acc.x = aself * v.x; acc.y = aself * v.y;
    }
    int rs = g_rowstart[n], re = g_rowstart[n + 1];
    for (int e = rs; e < re; e += 4) {
        int s = 0; float a = 0.f;
        if (lane < 4 && e + lane < re) {
            s = g_csr[e + lane];
            a = __expf(lrelu(g_a2s[s] + adn));
        }
#pragma unroll
        for (int j = 0; j < 4; j++) {
            if (e + j >= re) break;
            int sj   = __shfl_sync(0xffffffffu, s, j);
            float aj = __shfl_sync(0xffffffffu, a, j);
            S += aj;
            if (actc) {
                float2 v = *(const float2*)(g_h3 + (size_t)sj * NCLS + lane * 2);
                acc.x = fmaf(aj, v.x, acc.x);
                acc.y = fmaf(aj, v.y, acc.y);
            }
        }
    }
    float sinv = 1.f / (S + 1e-16f);
    float vx = -1e30f, vy = -1e30f;
    if (actc) {
        float2 bb = *(const float2*)(b2 + lane * 2);
        vx = acc.x * sinv + bb.x;
        vy = acc.y * sinv + bb.y;
    }
    float mx = fmaxf(vx, vy);
#pragma unroll
    for (int o = 16; o; o >>= 1) mx = fmaxf(mx, __shfl_xor_sync(0xffffffffu, mx, o));
    float s2 = actc ? (__expf(vx - mx) + __expf(vy - mx)) : 0.f;
#pragma unroll
    for (int o = 16; o; o >>= 1) s2 += __shfl_xor_sync(0xffffffffu, s2, o);
    float lg = logf(s2);
    if (actc) {
        float2 r; r.x = vx - mx - lg; r.y = vy - mx - lg;
        *(float2*)(out + n * NCLS + lane * 2) = r;
    }
}

// ---------------- launcher ----------------
extern "C" void kernel_launch(void* const* d_in, const int* in_sizes, int n_in,
                              void* d_out, int out_size) {
    const float* x    = (const float*)d_in[0];
    const void*  ei   = d_in[1];
    const float* W1   = (const float*)d_in[2];
    const float* a1sw = (const float*)d_in[3];
    const float* a1dw = (const float*)d_in[4];
    const float* b1   = (const float*)d_in[5];
    const float* W2   = (const float*)d_in[6];
    const float* a2sw = (const float*)d_in[7];
    const float* a2dw = (const float*)d_in[8];
    const float* b2   = (const float*)d_in[9];
    float* out = (float*)d_out;

    k_init<<<(NN + 255) / 256, 256>>>(ei);                       // 1
    k_deg<<<(EE + 255) / 256, 256>>>(ei);                        // 2
    k_scan<<<1, 1024>>>();                                       // 3
    k_gemm1<<<(NN + 63) / 64, 256>>>(x, W1, a1sw, a1dw);         // 4 (profiled slot)
    k_scatter<<<(EE + 255) / 256, 256>>>(ei);                    // 5
    k_gather1<<<NN, 256>>>(b1);                                  // 6
    k_gemm2<<<(NN + 127) / 128, 256>>>(W2, a2sw, a2dw);          // 7
    k_gather2<<<(NN + 3) / 4, 128>>>(b2, out);                   // 8
}

// round 7
// speedup vs baseline: 1.4852x; 1.2328x over previous
#include <cuda_runtime.h>
#include <math.h>

#define NN 50000
#define EE 800000
#define NF 128
#define NH 8
#define F1 256   // NH*NCH
#define NCLS 40
#define SCAN_B 49  // 49 * 1024 = 50176 >= NN

__device__ float g_h1[NN * F1];
__device__ float g_h2[NN * F1];
__device__ float g_h3[NN * NCLS];
__device__ float g_a1s[NN * NH];
__device__ float g_a1d[NN * NH];
__device__ float g_a2s[NN];
__device__ float g_a2d[NN];
__device__ int   g_deg[NN];
__device__ int   g_rowstart[NN + 1];
__device__ int   g_cursor[NN];
__device__ int   g_csr[EE];
__device__ int   g_bsum[SCAN_B];
__device__ int   g_is64;

__device__ __forceinline__ float lrelu(float x) { return x > 0.f ? x : 0.2f * x; }

// ---------------- init: zero degree + detect edge_index dtype ----------------
__global__ void k_init(const void* ei) {
    int i = blockIdx.x * blockDim.x + threadIdx.x;
    if (i < NN) g_deg[i] = 0;
    if (i == 0) {
        const unsigned long long* p = (const unsigned long long*)ei;
        int ok = 1;
        for (int j = 0; j < 64; j++)
            if (p[j] >= (unsigned long long)NN) ok = 0;
        g_is64 = ok;
    }
}

__device__ __forceinline__ int edge_val(const void* ei, long long idx, int is64) {
    return is64 ? (int)((const long long*)ei)[idx] : ((const int*)ei)[idx];
}

// ---------------- CSR build ----------------
__global__ void k_deg(const void* ei) {
    int e = blockIdx.x * blockDim.x + threadIdx.x;
    if (e >= EE) return;
    int d = edge_val(ei, (long long)EE + e, g_is64);
    atomicAdd(&g_deg[d], 1);
}

// block sums of degree (phase A)
__global__ __launch_bounds__(1024) void k_scanA() {
    __shared__ int sh[1024];
    int idx = blockIdx.x * 1024 + threadIdx.x;
    int v = (idx < NN) ? g_deg[idx] : 0;
    sh[threadIdx.x] = v;
    __syncthreads();
    for (int o = 512; o; o >>= 1) {
        if (threadIdx.x < o) sh[threadIdx.x] += sh[threadIdx.x + o];
        __syncthreads();
    }
    if (threadIdx.x == 0) g_bsum[blockIdx.x] = sh[0];
}

// per-block exclusive scan + global offset (phase B)
__global__ __launch_bounds__(1024) void k_scanB() {
    __shared__ int sh[1024];
    __shared__ int offs;
    int b = blockIdx.x;
    int idx = b * 1024 + threadIdx.x;
    int v = (idx < NN) ? g_deg[idx] : 0;
    if (threadIdx.x == 0) {
        int o = 0;
        for (int i = 0; i < b; i++) o += g_bsum[i];
        offs = o;
    }
    sh[threadIdx.x] = v;
    __syncthreads();
    for (int o = 1; o < 1024; o <<= 1) {
        int t = (threadIdx.x >= o) ? sh[threadIdx.x - o] : 0;
        __syncthreads();
        sh[threadIdx.x] += t;
        __syncthreads();
    }
    int excl = offs + sh[threadIdx.x] - v;
    if (idx < NN) {
        g_rowstart[idx] = excl;
        g_cursor[idx]   = excl;
    }
    if (idx == NN - 1) g_rowstart[NN] = excl + v;
}

__global__ void k_scatter(const void* ei) {
    int e = blockIdx.x * blockDim.x + threadIdx.x;
    if (e >= EE) return;
    int is64 = g_is64;
    int s = edge_val(ei, e, is64);
    int d = edge_val(ei, (long long)EE + e, is64);
    int pos = atomicAdd(&g_cursor[d], 1);
    g_csr[pos] = s;
}

// ---------------- GEMM1: h1 = x @ W1 + fused attention logits ----------------
// 64x256 block tile, 256 threads; thread tile: rows {ty*4+i, 32+ty*4+i},
// cols {tx*4+j, 128+tx*4+j}. Inner loop: 4 LDS.128 + 64 FFMA per k.
__global__ __launch_bounds__(256) void k_gemm1(const float* __restrict__ x,
                                               const float* __restrict__ W,
                                               const float* __restrict__ asw,
                                               const float* __restrict__ adw) {
    __shared__ float xs[32][68];
    __shared__ float ws[32][256];
    int tid = threadIdx.x;
    int tx = tid & 31, ty = tid >> 5;
    int m0 = blockIdx.x * 64;
    float acc[8][8];
#pragma unroll
    for (int i = 0; i < 8; i++)
#pragma unroll
        for (int j = 0; j < 8; j++) acc[i][j] = 0.f;

    for (int ks = 0; ks < NF; ks += 32) {
        {
            int r  = tid >> 2;
            int c4 = (tid & 3) << 3;
            int gm = m0 + r;
            float4 v0, v1;
            if (gm < NN) {
                const float4* px = (const float4*)(x + (long long)gm * NF + ks + c4);
                v0 = px[0]; v1 = px[1];
            } else {
                v0 = make_float4(0, 0, 0, 0); v1 = v0;
            }
            xs[c4 + 0][r] = v0.x; xs[c4 + 1][r] = v0.y;
            xs[c4 + 2][r] = v0.z; xs[c4 + 3][r] = v0.w;
            xs[c4 + 4][r] = v1.x; xs[c4 + 5][r] = v1.y;
            xs[c4 + 6][r] = v1.z; xs[c4 + 7][r] = v1.w;
        }
#pragma unroll
        for (int it = 0; it < 8; it++) {
            int f4 = it * 256 + tid;
            int k = f4 >> 6, c4 = f4 & 63;
            float4 wv = ((const float4*)(W + (long long)(ks + k) * F1))[c4];
            *((float4*)&ws[k][c4 << 2]) = wv;
        }
        __syncthreads();
#pragma unroll
        for (int k = 0; k < 32; k++) {
            const float4* xk = (const float4*)&xs[k][0];
            const float4* wk = (const float4*)&ws[k][0];
            float4 a0 = xk[ty];
            float4 a1 = xk[8 + ty];
            float4 b0 = wk[tx];
            float4 b1 = wk[32 + tx];
            float av[8] = {a0.x, a0.y, a0.z, a0.w, a1.x, a1.y, a1.z, a1.w};
            float bv[8] = {b0.x, b0.y, b0.z, b0.w, b1.x, b1.y, b1.z, b1.w};
#pragma unroll
            for (int i = 0; i < 8; i++)
#pragma unroll
                for (int j = 0; j < 8; j++)
                    acc[i][j] = fmaf(av[i], bv[j], acc[i][j]);
        }
        __syncthreads();
    }

    int c_lo = tx * 4, c_hi = 128 + tx * 4;
    float was[8], wad[8];
#pragma unroll
    for (int j = 0; j < 4; j++) {
        was[j]     = asw[c_lo + j];
        was[4 + j] = asw[c_hi + j];
        wad[j]     = adw[c_lo + j];
        wad[4 + j] = adw[c_hi + j];
    }
    int hd = tx >> 3;

#pragma unroll
    for (int i = 0; i < 8; i++) {
        int gm = m0 + ((i < 4) ? (ty * 4 + i) : (32 + ty * 4 + (i - 4)));
        bool ok = gm < NN;
        if (ok) {
            float4 r0 = make_float4(acc[i][0], acc[i][1], acc[i][2], acc[i][3]);
            float4 r1 = make_float4(acc[i][4], acc[i][5], acc[i][6], acc[i][7]);
            *(float4*)(g_h1 + (size_t)gm * F1 + c_lo) = r0;
            *(float4*)(g_h1 + (size_t)gm * F1 + c_hi) = r1;
        }
        float vs0 = 0.f, vd0 = 0.f, vs1 = 0.f, vd1 = 0.f;
#pragma unroll
        for (int j = 0; j < 4; j++) {
            vs0 = fmaf(acc[i][j], was[j], vs0);
            vd0 = fmaf(acc[i][j], wad[j], vd0);
            vs1 = fmaf(acc[i][4 + j], was[4 + j], vs1);
            vd1 = fmaf(acc[i][4 + j], wad[4 + j], vd1);
        }
#pragma unroll
        for (int o = 4; o; o >>= 1) {
            vs0 += __shfl_xor_sync(0xffffffffu, vs0, o);
            vd0 += __shfl_xor_sync(0xffffffffu, vd0, o);
            vs1 += __shfl_xor_sync(0xffffffffu, vs1, o);
            vd1 += __shfl_xor_sync(0xffffffffu, vd1, o);
        }
        if ((tx & 7) == 0 && ok) {
            g_a1s[gm * NH + hd]     = vs0;
            g_a1d[gm * NH + hd]     = vd0;
            g_a1s[gm * NH + 4 + hd] = vs1;
            g_a1d[gm * NH + 4 + hd] = vd1;
        }
    }
}

// ---------------- layer-1: fused softmax + aggregation + bias + ELU ----------------
// block = node (8 warps, warp = head). 32-edge smem-staged chunks:
//   warp0: csr -> ssh (coalesced, MLP 32)
//   all 256: alpha matrix ash[32][8] (one LDG + exp each, MLP 32)
//   gather: groups of 8 lanes, addresses from smem -> 8 independent LDG.128/warp
__global__ __launch_bounds__(256) void k_gather1(const float* __restrict__ b1) {
    __shared__ int   ssh[32];
    __shared__ float ash[32][8];
    __shared__ float adsh[8];
    __shared__ float assh[8];
    int n = blockIdx.x;
    int tid = threadIdx.x;
    int h = tid >> 5;
    int lane = tid & 31;
    int g = lane >> 3, l = lane & 7;
    int off = h * 32 + l * 4;
    if (tid < 8) {
        adsh[tid] = g_a1d[n * NH + tid];
        assh[tid] = g_a1s[n * NH + tid];
    }
    __syncthreads();
    float ad = adsh[h];
    float4 acc = make_float4(0.f, 0.f, 0.f, 0.f);
    float S = 0.f;
    if (g == 0) {   // self-loop handled by group 0
        float aself = __expf(lrelu(assh[h] + ad));
        float4 v = *(const float4*)(g_h1 + (size_t)n * F1 + off);
        acc.x = aself * v.x; acc.y = aself * v.y;
        acc.z = aself * v.z; acc.w = aself * v.w;
        S = aself;
    }
    int rs = g_rowstart[n], re = g_rowstart[n + 1];
    for (int base = rs; base < re; base += 32) {
        int cnt = min(32, re - base);
        if (tid < 32 && base + tid < re) ssh[tid] = g_csr[base + tid];
        __syncthreads();
        {
            int el = tid >> 3, hh = tid & 7;
            if (el < cnt) {
                int s = ssh[el];
                ash[el][hh] = __expf(lrelu(g_a1s[s * NH + hh] + adsh[hh]));
            }
        }
        __syncthreads();
#pragma unroll 4
        for (int t0 = 0; t0 < cnt; t0 += 4) {
            int t = t0 + g;
            if (t < cnt) {
                int sj   = ssh[t];
                float aj = ash[t][h];
                float4 v = *(const float4*)(g_h1 + (size_t)sj * F1 + off);
                acc.x = fmaf(aj, v.x, acc.x);
                acc.y = fmaf(aj, v.y, acc.y);
                acc.z = fmaf(aj, v.z, acc.z);
                acc.w = fmaf(aj, v.w, acc.w);
                S += aj;
            }
        }
        __syncthreads();   // protect ssh/ash before next chunk
    }
    // reduce the 4 groups (lanes differing in bits 3..4 hold the same channels)
#pragma unroll
    for (int o = 8; o <= 16; o <<= 1) {
        acc.x += __shfl_xor_sync(0xffffffffu, acc.x, o);
        acc.y += __shfl_xor_sync(0xffffffffu, acc.y, o);
        acc.z += __shfl_xor_sync(0xffffffffu, acc.z, o);
        acc.w += __shfl_xor_sync(0xffffffffu, acc.w, o);
        S     += __shfl_xor_sync(0xffffffffu, S, o);
    }
    if (g == 0) {
        float sinv = 1.f / (S + 1e-16f);
        float4 bb = *(const float4*)(b1 + off);
        float4 r;
        r.x = acc.x * sinv + bb.x;
        r.y = acc.y * sinv + bb.y;
        r.z = acc.z * sinv + bb.z;
        r.w = acc.w * sinv + bb.w;
        r.x = (r.x > 0.f) ? r.x : expm1f(r.x);
        r.y = (r.y > 0.f) ? r.y : expm1f(r.y);
        r.z = (r.z > 0.f) ? r.z : expm1f(r.z);
        r.w = (r.w > 0.f) ? r.w : expm1f(r.w);
        *(float4*)(g_h2 + (size_t)n * F1 + off) = r;
    }
}

// ---------------- GEMM2: h3 = h2 @ W2 + a2 logits ----------------
__global__ __launch_bounds__(256) void k_gemm2(const float* __restrict__ W2,
                                               const float* __restrict__ a2sw,
                                               const float* __restrict__ a2dw) {
    __shared__ float hs[32][132];
    __shared__ float ws2[32][40];
    int tid = threadIdx.x;
    int tx = tid & 7, ty = tid >> 3;
    int m0 = blockIdx.x * 128;
    float acc[4][5];
#pragma unroll
    for (int i = 0; i < 4; i++)
#pragma unroll
        for (int j = 0; j < 5; j++) acc[i][j] = 0.f;

    for (int ks = 0; ks < F1; ks += 32) {
#pragma unroll
        for (int it = 0; it < 4; it++) {
            int f4 = it * 256 + tid;
            int r = f4 >> 3, c4 = f4 & 7;
            int gm = m0 + r;
            float4 v = make_float4(0, 0, 0, 0);
            if (gm < NN) v = *((const float4*)(g_h2 + (size_t)gm * F1 + ks + (c4 << 2)));
            hs[(c4 << 2) + 0][r] = v.x; hs[(c4 << 2) + 1][r] = v.y;
            hs[(c4 << 2) + 2][r] = v.z; hs[(c4 << 2) + 3][r] = v.w;
        }
#pragma unroll
        for (int it = 0; it < 5; it++) {
            int idx = it * 256 + tid;
            int k = idx / 40, c = idx % 40;
            ws2[k][c] = W2[(ks + k) * NCLS + c];
        }
        __syncthreads();
#pragma unroll
        for (int k = 0; k < 32; k++) {
            float4 a4 = ((const float4*)&hs[k][0])[ty];
            float av[4] = {a4.x, a4.y, a4.z, a4.w};
            float b[5];
#pragma unroll
            for (int j = 0; j < 5; j++) b[j] = ws2[k][tx + 8 * j];
#pragma unroll
            for (int i = 0; i < 4; i++)
#pragma unroll
                for (int j = 0; j < 5; j++) acc[i][j] = fmaf(av[i], b[j], acc[i][j]);
        }
        __syncthreads();
    }
#pragma unroll
    for (int i = 0; i < 4; i++) {
        int gm = m0 + ty * 4 + i;
        if (gm >= NN) continue;
        float pa = 0.f, pd = 0.f;
#pragma unroll
        for (int j = 0; j < 5; j++) {
            int c = tx + 8 * j;
            g_h3[(size_t)gm * NCLS + c] = acc[i][j];
            pa = fmaf(acc[i][j], a2sw[c], pa);
            pd = fmaf(acc[i][j], a2dw[c], pd);
        }
#pragma unroll
        for (int o = 4; o; o >>= 1) {
            pa += __shfl_xor_sync(0xffffffffu, pa, o, 8);
            pd += __shfl_xor_sync(0xffffffffu, pd, o, 8);
        }
        if (tx == 0) {
            g_a2s[gm] = pa;
            g_a2d[gm] = pd;
        }
    }
}

// ---------------- layer-2: fused softmax + gather + bias + log_softmax ----------------
// one warp per node; 32-edge register prefetch (csr+a2s+exp, MLP 32),
// then shfl-broadcast consume; h3 loads fully independent.
__global__ __launch_bounds__(128) void k_gather2(const float* __restrict__ b2,
                                                 float* __restrict__ out) {
    int n = blockIdx.x * 4 + (threadIdx.x >> 5);
    if (n >= NN) return;
    int lane = threadIdx.x & 31;
    bool actc = lane < 20;
    float adn = g_a2d[n];
    float aself = __expf(lrelu(g_a2s[n] + adn));
    float S = aself;
    float2 acc = make_float2(0.f, 0.f);
    if (actc) {
        float2 v = *(const float2*)(g_h3 + (size_t)n * NCLS + lane * 2);
        acc.x = aself * v.x; acc.y = aself * v.y;
    }
    int rs = g_rowstart[n], re = g_rowstart[n + 1];
    for (int base = rs; base < re; base += 32) {
        int cnt = min(32, re - base);
        int sv = 0; float av = 0.f;
        if (base + lane < re) {
            sv = g_csr[base + lane];
            av = __expf(lrelu(g_a2s[sv] + adn));
        }
        for (int t = 0; t < cnt; t++) {
            int sj   = __shfl_sync(0xffffffffu, sv, t);
            float aj = __shfl_sync(0xffffffffu, av, t);
            S += aj;
            if (actc) {
                float2 v = *(const float2*)(g_h3 + (size_t)sj * NCLS + lane * 2);
                acc.x = fmaf(aj, v.x, acc.x);
                acc.y = fmaf(aj, v.y, acc.y);
            }
        }
    }
    float sinv = 1.f / (S + 1e-16f);
    float vx = -1e30f, vy = -1e30f;
    if (actc) {
        float2 bb = *(const float2*)(b2 + lane * 2);
        vx = acc.x * sinv + bb.x;
        vy = acc.y * sinv + bb.y;
    }
    float mx = fmaxf(vx, vy);
#pragma unroll
    for (int o = 16; o; o >>= 1) mx = fmaxf(mx, __shfl_xor_sync(0xffffffffu, mx, o));
    float s2 = actc ? (__expf(vx - mx) + __expf(vy - mx)) : 0.f;
#pragma unroll
    for (int o = 16; o; o >>= 1) s2 += __shfl_xor_sync(0xffffffffu, s2, o);
    float lg = logf(s2);
    if (actc) {
        float2 r; r.x = vx - mx - lg; r.y = vy - mx - lg;
        *(float2*)(out + (size_t)n * NCLS + lane * 2) = r;
    }
}

// ---------------- launcher ----------------
extern "C" void kernel_launch(void* const* d_in, const int* in_sizes, int n_in,
                              void* d_out, int out_size) {
    const float* x    = (const float*)d_in[0];
    const void*  ei   = d_in[1];
    const float* W1   = (const float*)d_in[2];
    const float* a1sw = (const float*)d_in[3];
    const float* a1dw = (const float*)d_in[4];
    const float* b1   = (const float*)d_in[5];
    const float* W2   = (const float*)d_in[6];
    const float* a2sw = (const float*)d_in[7];
    const float* a2dw = (const float*)d_in[8];
    const float* b2   = (const float*)d_in[9];
    float* out = (float*)d_out;

    k_init<<<(NN + 255) / 256, 256>>>(ei);                       // 1
    k_deg<<<(EE + 255) / 256, 256>>>(ei);                        // 2
    k_scanA<<<SCAN_B, 1024>>>();                                 // 3
    k_gemm1<<<(NN + 63) / 64, 256>>>(x, W1, a1sw, a1dw);         // 4 (profiled slot)
    k_scanB<<<SCAN_B, 1024>>>();                                 // 5
    k_scatter<<<(EE + 255) / 256, 256>>>(ei);                    // 6
    k_gather1<<<NN, 256>>>(b1);                                  // 7
    k_gemm2<<<(NN + 127) / 128, 256>>>(W2, a2sw, a2dw);          // 8
    k_gather2<<<(NN + 3) / 4, 128>>>(b2, out);                   // 9
}

// round 8
// speedup vs baseline: 2.0612x; 1.3878x over previous
#include <cuda_runtime.h>
#include <math.h>

#define NN 50000
#define EE 800000
#define NF 128
#define NH 8
#define F1 256   // NH*NCH
#define NCLS 40
#define SCAN_B 49  // 49 * 1024 = 50176 >= NN

__device__ float g_h1[NN * F1];
__device__ float g_h2[NN * F1];
__device__ float g_h3[NN * NCLS];
__device__ float g_a1s[NN * NH];
__device__ float g_a1d[NN * NH];
__device__ float g_a2s[NN];
__device__ float g_a2d[NN];
__device__ int   g_deg[NN];
__device__ int   g_rowstart[NN + 1];
__device__ int   g_cursor[NN];
__device__ int   g_csr[EE];
__device__ int   g_bsum[SCAN_B];
__device__ int   g_is64;

__device__ __forceinline__ float lrelu(float x) { return x > 0.f ? x : 0.2f * x; }

// ---------------- init: zero degree + detect edge_index dtype ----------------
__global__ void k_init(const void* ei) {
    int i = blockIdx.x * blockDim.x + threadIdx.x;
    if (i < NN) g_deg[i] = 0;
    if (i == 0) {
        const unsigned long long* p = (const unsigned long long*)ei;
        int ok = 1;
        for (int j = 0; j < 64; j++)
            if (p[j] >= (unsigned long long)NN) ok = 0;
        g_is64 = ok;
    }
}

__device__ __forceinline__ int edge_val(const void* ei, long long idx, int is64) {
    return is64 ? (int)((const long long*)ei)[idx] : ((const int*)ei)[idx];
}

// ---------------- CSR build ----------------
__global__ void k_deg(const void* ei) {
    int e = blockIdx.x * blockDim.x + threadIdx.x;
    if (e >= EE) return;
    int d = edge_val(ei, (long long)EE + e, g_is64);
    atomicAdd(&g_deg[d], 1);
}

__global__ __launch_bounds__(1024) void k_scanA() {
    __shared__ int sh[1024];
    int idx = blockIdx.x * 1024 + threadIdx.x;
    int v = (idx < NN) ? g_deg[idx] : 0;
    sh[threadIdx.x] = v;
    __syncthreads();
    for (int o = 512; o; o >>= 1) {
        if (threadIdx.x < o) sh[threadIdx.x] += sh[threadIdx.x + o];
        __syncthreads();
    }
    if (threadIdx.x == 0) g_bsum[blockIdx.x] = sh[0];
}

__global__ __launch_bounds__(1024) void k_scanB() {
    __shared__ int sh[1024];
    __shared__ int offs;
    int b = blockIdx.x;
    int idx = b * 1024 + threadIdx.x;
    int v = (idx < NN) ? g_deg[idx] : 0;
    if (threadIdx.x == 0) {
        int o = 0;
        for (int i = 0; i < b; i++) o += g_bsum[i];
        offs = o;
    }
    sh[threadIdx.x] = v;
    __syncthreads();
    for (int o = 1; o < 1024; o <<= 1) {
        int t = (threadIdx.x >= o) ? sh[threadIdx.x - o] : 0;
        __syncthreads();
        sh[threadIdx.x] += t;
        __syncthreads();
    }
    int excl = offs + sh[threadIdx.x] - v;
    if (idx < NN) {
        g_rowstart[idx] = excl;
        g_cursor[idx]   = excl;
    }
    if (idx == NN - 1) g_rowstart[NN] = excl + v;
}

__global__ void k_scatter(const void* ei) {
    int e = blockIdx.x * blockDim.x + threadIdx.x;
    if (e >= EE) return;
    int is64 = g_is64;
    int s = edge_val(ei, e, is64);
    int d = edge_val(ei, (long long)EE + e, is64);
    int pos = atomicAdd(&g_cursor[d], 1);
    g_csr[pos] = s;
}

// ---------------- GEMM1: h1 = x @ W1 + fused attention logits ----------------
__global__ __launch_bounds__(256) void k_gemm1(const float* __restrict__ x,
                                               const float* __restrict__ W,
                                               const float* __restrict__ asw,
                                               const float* __restrict__ adw) {
    __shared__ float xs[32][68];
    __shared__ float ws[32][256];
    int tid = threadIdx.x;
    int tx = tid & 31, ty = tid >> 5;
    int m0 = blockIdx.x * 64;
    float acc[8][8];
#pragma unroll
    for (int i = 0; i < 8; i++)
#pragma unroll
        for (int j = 0; j < 8; j++) acc[i][j] = 0.f;

    for (int ks = 0; ks < NF; ks += 32) {
        {
            int r  = tid >> 2;
            int c4 = (tid & 3) << 3;
            int gm = m0 + r;
            float4 v0, v1;
            if (gm < NN) {
                const float4* px = (const float4*)(x + (long long)gm * NF + ks + c4);
                v0 = px[0]; v1 = px[1];
            } else {
                v0 = make_float4(0, 0, 0, 0); v1 = v0;
            }
            xs[c4 + 0][r] = v0.x; xs[c4 + 1][r] = v0.y;
            xs[c4 + 2][r] = v0.z; xs[c4 + 3][r] = v0.w;
            xs[c4 + 4][r] = v1.x; xs[c4 + 5][r] = v1.y;
            xs[c4 + 6][r] = v1.z; xs[c4 + 7][r] = v1.w;
        }
#pragma unroll
        for (int it = 0; it < 8; it++) {
            int f4 = it * 256 + tid;
            int k = f4 >> 6, c4 = f4 & 63;
            float4 wv = ((const float4*)(W + (long long)(ks + k) * F1))[c4];
            *((float4*)&ws[k][c4 << 2]) = wv;
        }
        __syncthreads();
#pragma unroll
        for (int k = 0; k < 32; k++) {
            const float4* xk = (const float4*)&xs[k][0];
            const float4* wk = (const float4*)&ws[k][0];
            float4 a0 = xk[ty];
            float4 a1 = xk[8 + ty];
            float4 b0 = wk[tx];
            float4 b1 = wk[32 + tx];
            float av[8] = {a0.x, a0.y, a0.z, a0.w, a1.x, a1.y, a1.z, a1.w};
            float bv[8] = {b0.x, b0.y, b0.z, b0.w, b1.x, b1.y, b1.z, b1.w};
#pragma unroll
            for (int i = 0; i < 8; i++)
#pragma unroll
                for (int j = 0; j < 8; j++)
                    acc[i][j] = fmaf(av[i], bv[j], acc[i][j]);
        }
        __syncthreads();
    }

    int c_lo = tx * 4, c_hi = 128 + tx * 4;
    float was[8], wad[8];
#pragma unroll
    for (int j = 0; j < 4; j++) {
        was[j]     = asw[c_lo + j];
        was[4 + j] = asw[c_hi + j];
        wad[j]     = adw[c_lo + j];
        wad[4 + j] = adw[c_hi + j];
    }
    int hd = tx >> 3;

#pragma unroll
    for (int i = 0; i < 8; i++) {
        int gm = m0 + ((i < 4) ? (ty * 4 + i) : (32 + ty * 4 + (i - 4)));
        bool ok = gm < NN;
        if (ok) {
            float4 r0 = make_float4(acc[i][0], acc[i][1], acc[i][2], acc[i][3]);
            float4 r1 = make_float4(acc[i][4], acc[i][5], acc[i][6], acc[i][7]);
            *(float4*)(g_h1 + (size_t)gm * F1 + c_lo) = r0;
            *(float4*)(g_h1 + (size_t)gm * F1 + c_hi) = r1;
        }
        float vs0 = 0.f, vd0 = 0.f, vs1 = 0.f, vd1 = 0.f;
#pragma unroll
        for (int j = 0; j < 4; j++) {
            vs0 = fmaf(acc[i][j], was[j], vs0);
            vd0 = fmaf(acc[i][j], wad[j], vd0);
            vs1 = fmaf(acc[i][4 + j], was[4 + j], vs1);
            vd1 = fmaf(acc[i][4 + j], wad[4 + j], vd1);
        }
#pragma unroll
        for (int o = 4; o; o >>= 1) {
            vs0 += __shfl_xor_sync(0xffffffffu, vs0, o);
            vd0 += __shfl_xor_sync(0xffffffffu, vd0, o);
            vs1 += __shfl_xor_sync(0xffffffffu, vs1, o);
            vd1 += __shfl_xor_sync(0xffffffffu, vd1, o);
        }
        if ((tx & 7) == 0 && ok) {
            g_a1s[gm * NH + hd]     = vs0;
            g_a1d[gm * NH + hd]     = vd0;
            g_a1s[gm * NH + 4 + hd] = vs1;
            g_a1d[gm * NH + 4 + hd] = vd1;
        }
    }
}

// ---------------- layer-1: warp-per-node fused softmax + aggregation ----------------
// Lane holds channels [lane*4,+4) and [128+lane*4,+4) -> heads lane/8 and 4+lane/8.
// Per edge: 1 shfl (src), 2 broadcast a1s loads, 2 exp, 2 LDG.128, 8 FFMA.
// S accumulates per lane (identical within 8-lane head group) -> no reductions.
__global__ __launch_bounds__(256) void k_gather1(const float* __restrict__ b1) {
    int n = blockIdx.x * 8 + (threadIdx.x >> 5);
    if (n >= NN) return;
    int lane = threadIdx.x & 31;
    int c_lo = lane * 4, c_hi = 128 + lane * 4;
    int hd0 = lane >> 3, hd1 = 4 + hd0;

    float ad0 = g_a1d[n * NH + hd0];
    float ad1 = g_a1d[n * NH + hd1];
    float a0 = __expf(lrelu(g_a1s[n * NH + hd0] + ad0));
    float a1 = __expf(lrelu(g_a1s[n * NH + hd1] + ad1));
    float4 v0 = *(const float4*)(g_h1 + (size_t)n * F1 + c_lo);
    float4 v1 = *(const float4*)(g_h1 + (size_t)n * F1 + c_hi);
    float4 acc0 = make_float4(a0 * v0.x, a0 * v0.y, a0 * v0.z, a0 * v0.w);
    float4 acc1 = make_float4(a1 * v1.x, a1 * v1.y, a1 * v1.z, a1 * v1.w);
    float S0 = a0, S1 = a1;

    int rs = g_rowstart[n], re = g_rowstart[n + 1];
    for (int base = rs; base < re; base += 32) {
        int cnt = min(32, re - base);
        int sv = (base + lane < re) ? g_csr[base + lane] : 0;
#pragma unroll 4
        for (int t = 0; t < cnt; t++) {
            int s = __shfl_sync(0xffffffffu, sv, t);
            float e0 = __expf(lrelu(g_a1s[s * NH + hd0] + ad0));
            float e1 = __expf(lrelu(g_a1s[s * NH + hd1] + ad1));
            float4 w0 = *(const float4*)(g_h1 + (size_t)s * F1 + c_lo);
            float4 w1 = *(const float4*)(g_h1 + (size_t)s * F1 + c_hi);
            acc0.x = fmaf(e0, w0.x, acc0.x);
            acc0.y = fmaf(e0, w0.y, acc0.y);
            acc0.z = fmaf(e0, w0.z, acc0.z);
            acc0.w = fmaf(e0, w0.w, acc0.w);
            acc1.x = fmaf(e1, w1.x, acc1.x);
            acc1.y = fmaf(e1, w1.y, acc1.y);
            acc1.z = fmaf(e1, w1.z, acc1.z);
            acc1.w = fmaf(e1, w1.w, acc1.w);
            S0 += e0;
            S1 += e1;
        }
    }

    float i0 = 1.f / (S0 + 1e-16f);
    float i1 = 1.f / (S1 + 1e-16f);
    float4 bl = *(const float4*)(b1 + c_lo);
    float4 bh = *(const float4*)(b1 + c_hi);
    float4 r0, r1;
    r0.x = acc0.x * i0 + bl.x; r0.y = acc0.y * i0 + bl.y;
    r0.z = acc0.z * i0 + bl.z; r0.w = acc0.w * i0 + bl.w;
    r1.x = acc1.x * i1 + bh.x; r1.y = acc1.y * i1 + bh.y;
    r1.z = acc1.z * i1 + bh.z; r1.w = acc1.w * i1 + bh.w;
    r0.x = (r0.x > 0.f) ? r0.x : expm1f(r0.x);
    r0.y = (r0.y > 0.f) ? r0.y : expm1f(r0.y);
    r0.z = (r0.z > 0.f) ? r0.z : expm1f(r0.z);
    r0.w = (r0.w > 0.f) ? r0.w : expm1f(r0.w);
    r1.x = (r1.x > 0.f) ? r1.x : expm1f(r1.x);
    r1.y = (r1.y > 0.f) ? r1.y : expm1f(r1.y);
    r1.z = (r1.z > 0.f) ? r1.z : expm1f(r1.z);
    r1.w = (r1.w > 0.f) ? r1.w : expm1f(r1.w);
    *(float4*)(g_h2 + (size_t)n * F1 + c_lo) = r0;
    *(float4*)(g_h2 + (size_t)n * F1 + c_hi) = r1;
}

// ---------------- GEMM2: h3 = h2 @ W2 + a2 logits ----------------
__global__ __launch_bounds__(256) void k_gemm2(const float* __restrict__ W2,
                                               const float* __restrict__ a2sw,
                                               const float* __restrict__ a2dw) {
    __shared__ float hs[32][132];
    __shared__ float ws2[32][40];
    int tid = threadIdx.x;
    int tx = tid & 7, ty = tid >> 3;
    int m0 = blockIdx.x * 128;
    float acc[4][5];
#pragma unroll
    for (int i = 0; i < 4; i++)
#pragma unroll
        for (int j = 0; j < 5; j++) acc[i][j] = 0.f;

    for (int ks = 0; ks < F1; ks += 32) {
#pragma unroll
        for (int it = 0; it < 4; it++) {
            int f4 = it * 256 + tid;
            int r = f4 >> 3, c4 = f4 & 7;
            int gm = m0 + r;
            float4 v = make_float4(0, 0, 0, 0);
            if (gm < NN) v = *((const float4*)(g_h2 + (size_t)gm * F1 + ks + (c4 << 2)));
            hs[(c4 << 2) + 0][r] = v.x; hs[(c4 << 2) + 1][r] = v.y;
            hs[(c4 << 2) + 2][r] = v.z; hs[(c4 << 2) + 3][r] = v.w;
        }
#pragma unroll
        for (int it = 0; it < 5; it++) {
            int idx = it * 256 + tid;
            int k = idx / 40, c = idx % 40;
            ws2[k][c] = W2[(ks + k) * NCLS + c];
        }
        __syncthreads();
#pragma unroll
        for (int k = 0; k < 32; k++) {
            float4 a4 = ((const float4*)&hs[k][0])[ty];
            float av[4] = {a4.x, a4.y, a4.z, a4.w};
            float b[5];
#pragma unroll
            for (int j = 0; j < 5; j++) b[j] = ws2[k][tx + 8 * j];
#pragma unroll
            for (int i = 0; i < 4; i++)
#pragma unroll
                for (int j = 0; j < 5; j++) acc[i][j] = fmaf(av[i], b[j], acc[i][j]);
        }
        __syncthreads();
    }
#pragma unroll
    for (int i = 0; i < 4; i++) {
        int gm = m0 + ty * 4 + i;
        if (gm >= NN) continue;
        float pa = 0.f, pd = 0.f;
#pragma unroll
        for (int j = 0; j < 5; j++) {
            int c = tx + 8 * j;
            g_h3[(size_t)gm * NCLS + c] = acc[i][j];
            pa = fmaf(acc[i][j], a2sw[c], pa);
            pd = fmaf(acc[i][j], a2dw[c], pd);
        }
#pragma unroll
        for (int o = 4; o; o >>= 1) {
            pa += __shfl_xor_sync(0xffffffffu, pa, o, 8);
            pd += __shfl_xor_sync(0xffffffffu, pd, o, 8);
        }
        if (tx == 0) {
            g_a2s[gm] = pa;
            g_a2d[gm] = pd;
        }
    }
}

// ---------------- layer-2: warp-per-node softmax + gather + log_softmax ----------------
__global__ __launch_bounds__(128) void k_gather2(const float* __restrict__ b2,
                                                 float* __restrict__ out) {
    int n = blockIdx.x * 4 + (threadIdx.x >> 5);
    if (n >= NN) return;
    int lane = threadIdx.x & 31;
    bool actc = lane < 20;
    float adn = g_a2d[n];
    float aself = __expf(lrelu(g_a2s[n] + adn));
    float S = aself;
    float2 acc = make_float2(0.f, 0.f);
    if (actc) {
        float2 v = *(const float2*)(g_h3 + (size_t)n * NCLS + lane * 2);
        acc.x = aself * v.x; acc.y = aself * v.y;
    }
    int rs = g_rowstart[n], re = g_rowstart[n + 1];
    for (int base = rs; base < re; base += 32) {
        int cnt = min(32, re - base);
        int sv = 0; float av = 0.f;
        if (base + lane < re) {
            sv = g_csr[base + lane];
            av = __expf(lrelu(g_a2s[sv] + adn));
        }
        for (int t = 0; t < cnt; t++) {
            int sj   = __shfl_sync(0xffffffffu, sv, t);
            float aj = __shfl_sync(0xffffffffu, av, t);
            S += aj;
            if (actc) {
                float2 v = *(const float2*)(g_h3 + (size_t)sj * NCLS + lane * 2);
                acc.x = fmaf(aj, v.x, acc.x);
                acc.y = fmaf(aj, v.y, acc.y);
            }
        }
    }
    float sinv = 1.f / (S + 1e-16f);
    float vx = -1e30f, vy = -1e30f;
    if (actc) {
        float2 bb = *(const float2*)(b2 + lane * 2);
        vx = acc.x * sinv + bb.x;
        vy = acc.y * sinv + bb.y;
    }
    float mx = fmaxf(vx, vy);
#pragma unroll
    for (int o = 16; o; o >>= 1) mx = fmaxf(mx, __shfl_xor_sync(0xffffffffu, mx, o));
    float s2 = actc ? (__expf(vx - mx) + __expf(vy - mx)) : 0.f;
#pragma unroll
    for (int o = 16; o; o >>= 1) s2 += __shfl_xor_sync(0xffffffffu, s2, o);
    float lg = logf(s2);
    if (actc) {
        float2 r; r.x = vx - mx - lg; r.y = vy - mx - lg;
        *(float2*)(out + (size_t)n * NCLS + lane * 2) = r;
    }
}

// ---------------- launcher ----------------
extern "C" void kernel_launch(void* const* d_in, const int* in_sizes, int n_in,
                              void* d_out, int out_size) {
    const float* x    = (const float*)d_in[0];
    const void*  ei   = d_in[1];
    const float* W1   = (const float*)d_in[2];
    const float* a1sw = (const float*)d_in[3];
    const float* a1dw = (const float*)d_in[4];
    const float* b1   = (const float*)d_in[5];
    const float* W2   = (const float*)d_in[6];
    const float* a2sw = (const float*)d_in[7];
    const float* a2dw = (const float*)d_in[8];
    const float* b2   = (const float*)d_in[9];
    float* out = (float*)d_out;

    k_init<<<(NN + 255) / 256, 256>>>(ei);                       // 1
    k_deg<<<(EE + 255) / 256, 256>>>(ei);                        // 2
    k_scanA<<<SCAN_B, 1024>>>();                                 // 3
    k_gemm1<<<(NN + 63) / 64, 256>>>(x, W1, a1sw, a1dw);         // 4 (profiled slot)
    k_scanB<<<SCAN_B, 1024>>>();                                 // 5
    k_scatter<<<(EE + 255) / 256, 256>>>(ei);                    // 6
    k_gather1<<<(NN + 7) / 8, 256>>>(b1);                        // 7
    k_gemm2<<<(NN + 127) / 128, 256>>>(W2, a2sw, a2dw);          // 8
    k_gather2<<<(NN + 3) / 4, 128>>>(b2, out);                   // 9
}